// round 14
// baseline (speedup 1.0000x reference)
#include <cuda_runtime.h>
#include <cuda_bf16.h>
#include <cstdint>
#include <math.h>

#define BB 2
#define TT 2048
#define EE 1024
#define HH 16
#define DH 64
#define MM (BB*TT)   // 4096

// Scratch (__device__ globals; allocations are forbidden)
__device__ float          g_x1 [MM*EE];         // attn+residual output (f32, final residual)
__device__ __nv_bfloat16  g_x1h[MM*EE];         // same in bf16 (FFN A operand)
__device__ __nv_bfloat16  g_xh [MM*EE];         // x in bf16 (QKV A operand)
__device__ __nv_bfloat16  g_qh [MM*EE];
__device__ __nv_bfloat16  g_kh [MM*EE];
__device__ __nv_bfloat16  g_vh [MM*EE];
__device__ __nv_bfloat16  g_wh4[4*EE*EE];       // Wq,Wk,Wv,Wf bf16, NATURAL [k][n] layout

// ---------------------------------------------------------------------------
// Baseline-PTX helpers (sm_80-era: mma.sync + cp.async + ldmatrix).
// ---------------------------------------------------------------------------
__device__ __forceinline__ uint32_t smem_u32(const void* p){
    uint32_t a;
    asm("{ .reg .u64 t; cvta.to.shared.u64 t, %1; cvt.u32.u64 %0, t; }":"=r"(a):"l"(p));
    return a;
}
#define CP16(dst,src)  asm volatile("cp.async.cg.shared.global [%0], [%1], 16;\n"::"r"(dst),"l"(src))
#define CP_COMMIT()    asm volatile("cp.async.commit_group;\n":::"memory")
#define CP_WAIT1()     asm volatile("cp.async.wait_group 1;\n":::"memory")
#define CP_WAIT0()     asm volatile("cp.async.wait_group 0;\n":::"memory")
#define LDSM4(r0,r1,r2,r3,addr) \
    asm volatile("ldmatrix.sync.aligned.m8n8.x4.shared.b16 {%0,%1,%2,%3}, [%4];" \
        :"=r"(r0),"=r"(r1),"=r"(r2),"=r"(r3):"r"(addr))
#define LDSM4T(r0,r1,r2,r3,addr) \
    asm volatile("ldmatrix.sync.aligned.m8n8.x4.trans.shared.b16 {%0,%1,%2,%3}, [%4];" \
        :"=r"(r0),"=r"(r1),"=r"(r2),"=r"(r3):"r"(addr))

__device__ __forceinline__ void mma_bf16(float c[4], uint32_t a0, uint32_t a1,
                                         uint32_t a2, uint32_t a3,
                                         uint32_t b0, uint32_t b1){
    asm volatile(
        "mma.sync.aligned.m16n8k16.row.col.f32.bf16.bf16.f32 "
        "{%0,%1,%2,%3}, {%4,%5,%6,%7}, {%8,%9}, {%0,%1,%2,%3};\n"
        : "+f"(c[0]), "+f"(c[1]), "+f"(c[2]), "+f"(c[3])
        : "r"(a0), "r"(a1), "r"(a2), "r"(a3), "r"(b0), "r"(b1));
}
__device__ __forceinline__ float ex2f(float x){
    float y; asm("ex2.approx.f32 %0, %1;":"=f"(y):"f"(x)); return y;
}

// ---------------------------------------------------------------------------
// Prologue (single launch): f32 -> bf16 for x, Wq, Wk, Wv, Wf.
// 8M elements, 4 per thread.
// ---------------------------------------------------------------------------
#define XN (MM*EE)     // 4M
#define WN (EE*EE)     // 1M

__global__ void __launch_bounds__(256) cvt_all_kernel(const float* __restrict__ x,
                                                      const float* __restrict__ Wq,
                                                      const float* __restrict__ Wk,
                                                      const float* __restrict__ Wv,
                                                      const float* __restrict__ Wf)
{
    int i = (blockIdx.x * 256 + threadIdx.x) * 4;
    const float* src;
    __nv_bfloat16* dst;
    int off;
    if (i < XN) {
        src = x; dst = g_xh; off = i;
    } else {
        int j = i - XN;
        int slot = j >> 20;              // /WN -> 0..3
        off = j & (WN - 1);
        src = (slot == 0) ? Wq : (slot == 1) ? Wk : (slot == 2) ? Wv : Wf;
        dst = g_wh4 + (size_t)slot * WN;
    }
    float4 v = *reinterpret_cast<const float4*>(src + off);
    __nv_bfloat162 p0 = __floats2bfloat162_rn(v.x, v.y);
    __nv_bfloat162 p1 = __floats2bfloat162_rn(v.z, v.w);
    uint2 u;
    u.x = *reinterpret_cast<uint32_t*>(&p0);
    u.y = *reinterpret_cast<uint32_t*>(&p1);
    *reinterpret_cast<uint2*>(&dst[off]) = u;
}

// ---------------------------------------------------------------------------
// bf16 GEMM core layout constants (shared by QKV + FFN kernels).
// A rows padded to 80B; B (natural [k][n]) rows 512B + 16B pad.
// ---------------------------------------------------------------------------
#define HA_BYTES (128*80)          // 10240
#define WB_ROW   528
#define WB_BYTES (32*WB_ROW)       // 16896
#define HSTAGE   (HA_BYTES + WB_BYTES)   // 27136
#define BGEMM_SMEM (2*HSTAGE)      // 54272

// ---------------------------------------------------------------------------
// bf16 QKV GEMM (fused 3 projections): C = x @ W, bf16 out.
// ---------------------------------------------------------------------------
__global__ void __launch_bounds__(256) qkv_gemm()
{
    extern __shared__ char smc[];
    const uint32_t sbase = smem_u32(smc);
    const int tid  = threadIdx.x;
    const int wid  = tid >> 5, lane = tid & 31;
    const int ty   = lane >> 2, tx = lane & 3;
    const int wm   = wid >> 2;
    const int wn   = wid & 3;
    const int row0 = blockIdx.y * 128;
    const int sel  = blockIdx.x >> 2;
    const int col0 = (blockIdx.x & 3) * 256;
    const __nv_bfloat16* Wt = g_wh4 + (size_t)sel * WN;   // [k][n]
    __nv_bfloat16* C = (sel == 0) ? g_qh : (sel == 1) ? g_kh : g_vh;

    float c[4][8][4];
    #pragma unroll
    for (int mf = 0; mf < 4; mf++)
        #pragma unroll
        for (int nf = 0; nf < 8; nf++)
            #pragma unroll
            for (int u = 0; u < 4; u++) c[mf][nf][u] = 0.f;

    auto load_tiles = [&](int st, int k0){
        uint32_t sA = sbase + st * HSTAGE;
        uint32_t sB = sA + HA_BYTES;
        #pragma unroll
        for (int t = 0; t < 2; t++) {               // A: 128 rows x 4 chunks (32 bf16)
            int s = tid + t * 256;
            int r = s >> 2, ch = s & 3;
            CP16(sA + (uint32_t)(r * 80 + ch * 16),
                 g_xh + (size_t)(row0 + r) * EE + k0 + ch * 8);
        }
        #pragma unroll
        for (int t = 0; t < 4; t++) {               // B: 32 k-rows x 32 chunks (256 bf16)
            int s = tid + t * 256;
            int r = s >> 5, ch = s & 31;
            CP16(sB + (uint32_t)(r * WB_ROW + ch * 16),
                 Wt + (size_t)(k0 + r) * EE + col0 + ch * 8);
        }
    };

    load_tiles(0, 0);
    CP_COMMIT();

    for (int kt = 0; kt < 32; kt++) {
        const int b = kt & 1;
        if (kt + 1 < 32) {
            load_tiles(1 - b, (kt + 1) << 5);
            CP_COMMIT();
            CP_WAIT1();
        } else {
            CP_WAIT0();
        }
        __syncthreads();

        const uint32_t sA = sbase + b * HSTAGE;
        const uint32_t sB = sA + HA_BYTES;

        #pragma unroll
        for (int ks = 0; ks < 2; ks++) {
            uint32_t a[4][4];
            #pragma unroll
            for (int mf = 0; mf < 4; mf++) {
                uint32_t row = wm * 64 + mf * 16 + (lane & 15);
                uint32_t kh  = ks * 16 + ((lane & 16) >> 1);
                LDSM4(a[mf][0], a[mf][1], a[mf][2], a[mf][3],
                      sA + row * 80 + kh * 2);
            }
            uint32_t bfr[8][2];
            #pragma unroll
            for (int p = 0; p < 4; p++) {
                uint32_t krow = ks * 16 + (lane & 15);
                uint32_t nh   = wn * 64 + p * 16 + ((lane & 16) >> 1);
                LDSM4T(bfr[2*p][0], bfr[2*p][1], bfr[2*p+1][0], bfr[2*p+1][1],
                       sB + krow * WB_ROW + nh * 2);
            }
            #pragma unroll
            for (int mf = 0; mf < 4; mf++)
                #pragma unroll
                for (int nf = 0; nf < 8; nf++)
                    mma_bf16(c[mf][nf], a[mf][0], a[mf][1], a[mf][2], a[mf][3],
                             bfr[nf][0], bfr[nf][1]);
        }
        __syncthreads();
    }

    #pragma unroll
    for (int mf = 0; mf < 4; mf++) {
        const int r = row0 + wm * 64 + mf * 16 + ty;
        #pragma unroll
        for (int nf = 0; nf < 8; nf++) {
            const int cc = col0 + wn * 64 + nf * 8 + (tx << 1);
            __nv_bfloat162 p0 = __floats2bfloat162_rn(c[mf][nf][0], c[mf][nf][1]);
            __nv_bfloat162 p1 = __floats2bfloat162_rn(c[mf][nf][2], c[mf][nf][3]);
            *reinterpret_cast<__nv_bfloat162*>(&C[(size_t)r * EE + cc]) = p0;
            *reinterpret_cast<__nv_bfloat162*>(&C[(size_t)(r + 8) * EE + cc]) = p1;
        }
    }
}

// ---------------------------------------------------------------------------
// bf16 FFN GEMM: out = x1 + relu(x1 @ Wf + bias), f32 out.
// A = g_x1h (bf16, written by attn epilogue), B = g_wh4[3] natural [k][n].
// Residual + bias in f32 from g_x1 / bias.
// ---------------------------------------------------------------------------
__global__ void __launch_bounds__(256) ffn_gemm(float* __restrict__ out,
                                                const float* __restrict__ bias)
{
    extern __shared__ char smc[];
    const uint32_t sbase = smem_u32(smc);
    const int tid  = threadIdx.x;
    const int wid  = tid >> 5, lane = tid & 31;
    const int ty   = lane >> 2, tx = lane & 3;
    const int wm   = wid >> 2;
    const int wn   = wid & 3;
    const int row0 = blockIdx.y * 128;
    const int col0 = blockIdx.x * 256;
    const __nv_bfloat16* Wt = g_wh4 + (size_t)3 * WN;

    float c[4][8][4];
    #pragma unroll
    for (int mf = 0; mf < 4; mf++)
        #pragma unroll
        for (int nf = 0; nf < 8; nf++)
            #pragma unroll
            for (int u = 0; u < 4; u++) c[mf][nf][u] = 0.f;

    auto load_tiles = [&](int st, int k0){
        uint32_t sA = sbase + st * HSTAGE;
        uint32_t sB = sA + HA_BYTES;
        #pragma unroll
        for (int t = 0; t < 2; t++) {
            int s = tid + t * 256;
            int r = s >> 2, ch = s & 3;
            CP16(sA + (uint32_t)(r * 80 + ch * 16),
                 g_x1h + (size_t)(row0 + r) * EE + k0 + ch * 8);
        }
        #pragma unroll
        for (int t = 0; t < 4; t++) {
            int s = tid + t * 256;
            int r = s >> 5, ch = s & 31;
            CP16(sB + (uint32_t)(r * WB_ROW + ch * 16),
                 Wt + (size_t)(k0 + r) * EE + col0 + ch * 8);
        }
    };

    load_tiles(0, 0);
    CP_COMMIT();

    for (int kt = 0; kt < 32; kt++) {
        const int b = kt & 1;
        if (kt + 1 < 32) {
            load_tiles(1 - b, (kt + 1) << 5);
            CP_COMMIT();
            CP_WAIT1();
        } else {
            CP_WAIT0();
        }
        __syncthreads();

        const uint32_t sA = sbase + b * HSTAGE;
        const uint32_t sB = sA + HA_BYTES;

        #pragma unroll
        for (int ks = 0; ks < 2; ks++) {
            uint32_t a[4][4];
            #pragma unroll
            for (int mf = 0; mf < 4; mf++) {
                uint32_t row = wm * 64 + mf * 16 + (lane & 15);
                uint32_t kh  = ks * 16 + ((lane & 16) >> 1);
                LDSM4(a[mf][0], a[mf][1], a[mf][2], a[mf][3],
                      sA + row * 80 + kh * 2);
            }
            uint32_t bfr[8][2];
            #pragma unroll
            for (int p = 0; p < 4; p++) {
                uint32_t krow = ks * 16 + (lane & 15);
                uint32_t nh   = wn * 64 + p * 16 + ((lane & 16) >> 1);
                LDSM4T(bfr[2*p][0], bfr[2*p][1], bfr[2*p+1][0], bfr[2*p+1][1],
                       sB + krow * WB_ROW + nh * 2);
            }
            #pragma unroll
            for (int mf = 0; mf < 4; mf++)
                #pragma unroll
                for (int nf = 0; nf < 8; nf++)
                    mma_bf16(c[mf][nf], a[mf][0], a[mf][1], a[mf][2], a[mf][3],
                             bfr[nf][0], bfr[nf][1]);
        }
        __syncthreads();
    }

    #pragma unroll
    for (int mf = 0; mf < 4; mf++) {
        const int r = row0 + wm * 64 + mf * 16 + ty;
        #pragma unroll
        for (int nf = 0; nf < 8; nf++) {
            const int cc = col0 + wn * 64 + nf * 8 + (tx << 1);
            float2 bb = *reinterpret_cast<const float2*>(bias + cc);
            float2 x0 = *reinterpret_cast<const float2*>(&g_x1[(size_t)r * EE + cc]);
            float2 x1 = *reinterpret_cast<const float2*>(&g_x1[(size_t)(r + 8) * EE + cc]);
            float2 v0 = make_float2(x0.x + fmaxf(c[mf][nf][0] + bb.x, 0.f),
                                    x0.y + fmaxf(c[mf][nf][1] + bb.y, 0.f));
            float2 v1 = make_float2(x1.x + fmaxf(c[mf][nf][2] + bb.x, 0.f),
                                    x1.y + fmaxf(c[mf][nf][3] + bb.y, 0.f));
            *reinterpret_cast<float2*>(out + (size_t)r * EE + cc) = v0;
            *reinterpret_cast<float2*>(out + (size_t)(r + 8) * EE + cc) = v1;
        }
    }
}

// ---------------------------------------------------------------------------
// bf16 flash attention (causal, online softmax), all-ldmatrix fragments.
// Identical to the passing R12 kernel except the epilogue also writes g_x1h.
// ---------------------------------------------------------------------------
#define QT 128
#define AST 72                                  // halfwords per row
#define AT_BYTES (64*AST*2)                     // 9216 per stage
#define ATTN_SMEM (4*AT_BYTES)                  // 36864: KS[2] + VS[2]

__global__ void __launch_bounds__(256, 1) attn_tc(const float* __restrict__ x)
{
    extern __shared__ char smc[];
    const uint32_t sb_KS = smem_u32(smc);               // [2][64][72]h (Q staged here too)
    const uint32_t sb_VS = sb_KS + 2 * AT_BYTES;        // [2][64][72]h

    const int tid = threadIdx.x;
    const int wid = tid >> 5, lane = tid & 31;
    const int ty = lane >> 2, tx = lane & 3;
    const int bh = blockIdx.y, b = bh >> 4, h = bh & 15;
    const int qb = blockIdx.x * QT;
    const int ktmax = (qb + QT - 1) >> 6;
    const float sc2 = 0.03125f * 1.44269504088896f;     // 1/sqrt(1024) * log2e

    // ---- stage Q (128 rows x 8 chunks of 16B) through KS area ----
    {
        const __nv_bfloat16* Qg = g_qh + (size_t)(b * TT + qb) * EE + h * DH;
        #pragma unroll
        for (int t = 0; t < 4; t++) {
            int s = tid + t * 256;          // 0..1023
            int r = s >> 3, ch = s & 7;     // 128 rows x 8 chunks
            CP16(sb_KS + (uint32_t)(r * 144 + ch * 16), Qg + (size_t)r * EE + ch * 8);
        }
        CP_COMMIT(); CP_WAIT0();
    }
    __syncthreads();

    uint32_t qa[4][4];
    #pragma unroll
    for (int kf = 0; kf < 4; kf++) {
        uint32_t row = wid * 16 + (lane & 15);
        uint32_t kh  = kf * 16 + ((lane & 16) >> 1);
        LDSM4(qa[kf][0], qa[kf][1], qa[kf][2], qa[kf][3],
              sb_KS + row * 144 + kh * 2);
    }
    __syncthreads();

    float mrow[2] = {-1e30f, -1e30f};
    float lrow[2] = {0.f, 0.f};
    float o[8][4];
    #pragma unroll
    for (int df = 0; df < 8; df++)
        #pragma unroll
        for (int u = 0; u < 4; u++) o[df][u] = 0.f;

    auto issue_tile = [&](int kt){
        const __nv_bfloat16* Kg = g_kh + (size_t)(b * TT + kt * 64) * EE + h * DH;
        const __nv_bfloat16* Vg = g_vh + (size_t)(b * TT + kt * 64) * EE + h * DH;
        uint32_t dK = sb_KS + (uint32_t)((kt & 1) * AT_BYTES);
        uint32_t dV = sb_VS + (uint32_t)((kt & 1) * AT_BYTES);
        #pragma unroll
        for (int t = 0; t < 2; t++) {
            int s = tid + t * 256;          // 0..511
            int r = s >> 3, ch = s & 7;     // 64 rows x 8 chunks
            CP16(dK + (uint32_t)(r * 144 + ch * 16), Kg + (size_t)r * EE + ch * 8);
            CP16(dV + (uint32_t)(r * 144 + ch * 16), Vg + (size_t)r * EE + ch * 8);
        }
        CP_COMMIT();
    };

    issue_tile(0);
    issue_tile(1);

    for (int kt = 0; kt <= ktmax; kt++) {
        const int bs = kt & 1;
        if (kt < ktmax) { CP_WAIT1(); } else { CP_WAIT0(); }
        __syncthreads();

        const uint32_t sK = sb_KS + bs * AT_BYTES;
        const uint32_t sV = sb_VS + bs * AT_BYTES;

        // S = Q K^T (bf16 m16n8k16)
        float s[8][4];
        #pragma unroll
        for (int nf = 0; nf < 8; nf++)
            #pragma unroll
            for (int u = 0; u < 4; u++) s[nf][u] = 0.f;
        #pragma unroll
        for (int kf = 0; kf < 4; kf++) {
            uint32_t bk[8][2];
            #pragma unroll
            for (int p = 0; p < 4; p++) {
                uint32_t row = p * 16 + (lane & 7) + ((lane & 16) >> 1);
                uint32_t kh  = kf * 16 + (lane & 8);
                LDSM4(bk[2*p][0], bk[2*p][1], bk[2*p+1][0], bk[2*p+1][1],
                      sK + row * 144 + kh * 2);
            }
            #pragma unroll
            for (int nf = 0; nf < 8; nf++)
                mma_bf16(s[nf], qa[kf][0], qa[kf][1], qa[kf][2], qa[kf][3],
                         bk[nf][0], bk[nf][1]);
        }

        // scale + causal mask + row max
        const int q0 = qb + wid * 16;
        const bool need_mask = (kt * 64 + 63) > q0;
        float pmax[2] = {-1e30f, -1e30f};
        #pragma unroll
        for (int nf = 0; nf < 8; nf++) {
            int kkb = kt * 64 + nf * 8 + 2 * tx;
            #pragma unroll
            for (int u = 0; u < 4; u++) {
                float v = s[nf][u] * sc2;
                if (need_mask) {
                    int kkg = kkb + (u & 1);
                    int qg  = q0 + ty + ((u >> 1) << 3);
                    if (kkg > qg) v = -1e30f;
                }
                s[nf][u] = v;
                pmax[u >> 1] = fmaxf(pmax[u >> 1], v);
            }
        }
        #pragma unroll
        for (int r = 0; r < 2; r++) {
            pmax[r] = fmaxf(pmax[r], __shfl_xor_sync(0xffffffffu, pmax[r], 1));
            pmax[r] = fmaxf(pmax[r], __shfl_xor_sync(0xffffffffu, pmax[r], 2));
        }
        float mn0 = fmaxf(mrow[0], pmax[0]);
        float mn1 = fmaxf(mrow[1], pmax[1]);
        float cr0 = ex2f(mrow[0] - mn0);
        float cr1 = ex2f(mrow[1] - mn1);
        mrow[0] = mn0; mrow[1] = mn1;

        // P = 2^(s-m): pack bf16 A-frags + row sums
        uint32_t pa[4][4];
        float ls[2] = {0.f, 0.f};
        #pragma unroll
        for (int nf = 0; nf < 8; nf++) {
            float p0 = ex2f(s[nf][0] - mn0);
            float p1 = ex2f(s[nf][1] - mn0);
            float p2 = ex2f(s[nf][2] - mn1);
            float p3 = ex2f(s[nf][3] - mn1);
            ls[0] += p0 + p1;
            ls[1] += p2 + p3;
            __nv_bfloat162 t0 = __floats2bfloat162_rn(p0, p1);
            __nv_bfloat162 t1 = __floats2bfloat162_rn(p2, p3);
            uint32_t lo = *reinterpret_cast<uint32_t*>(&t0);
            uint32_t hi = *reinterpret_cast<uint32_t*>(&t1);
            int kb = nf >> 1;
            if ((nf & 1) == 0) { pa[kb][0] = lo; pa[kb][1] = hi; }
            else               { pa[kb][2] = lo; pa[kb][3] = hi; }
        }
        #pragma unroll
        for (int r = 0; r < 2; r++) {
            ls[r] += __shfl_xor_sync(0xffffffffu, ls[r], 1);
            ls[r] += __shfl_xor_sync(0xffffffffu, ls[r], 2);
        }
        lrow[0] = lrow[0] * cr0 + ls[0];
        lrow[1] = lrow[1] * cr1 + ls[1];

        // rescale O, then O += P @ V  (V via ldmatrix.trans)
        #pragma unroll
        for (int df = 0; df < 8; df++) {
            o[df][0] *= cr0; o[df][1] *= cr0;
            o[df][2] *= cr1; o[df][3] *= cr1;
        }
        #pragma unroll
        for (int kb = 0; kb < 4; kb++) {
            uint32_t vb[8][2];
            #pragma unroll
            for (int dp = 0; dp < 4; dp++) {
                uint32_t row = kb * 16 + (lane & 15);
                uint32_t dhh = dp * 16 + ((lane & 16) >> 1);
                LDSM4T(vb[2*dp][0], vb[2*dp][1], vb[2*dp+1][0], vb[2*dp+1][1],
                       sV + row * 144 + dhh * 2);
            }
            #pragma unroll
            for (int df = 0; df < 8; df++)
                mma_bf16(o[df], pa[kb][0], pa[kb][1], pa[kb][2], pa[kb][3],
                         vb[df][0], vb[df][1]);
        }
        __syncthreads();
        if (kt + 2 <= ktmax) issue_tile(kt + 2);
    }

    // epilogue: normalize + residual (f32 to g_x1, bf16 copy to g_x1h)
    const float inv0 = 1.f / lrow[0];
    const float inv1 = 1.f / lrow[1];
    const size_t base = (size_t)(b * TT + qb + wid * 16) * EE + h * DH;
    #pragma unroll
    for (int df = 0; df < 8; df++) {
        int col = df * 8 + 2 * tx;
        {
            size_t idx = base + (size_t)ty * EE + col;
            float2 xv = *reinterpret_cast<const float2*>(&x[idx]);
            float2 ov = make_float2(xv.x + o[df][0] * inv0, xv.y + o[df][1] * inv0);
            *reinterpret_cast<float2*>(&g_x1[idx]) = ov;
            __nv_bfloat162 hv = __floats2bfloat162_rn(ov.x, ov.y);
            *reinterpret_cast<__nv_bfloat162*>(&g_x1h[idx]) = hv;
        }
        {
            size_t idx = base + (size_t)(ty + 8) * EE + col;
            float2 xv = *reinterpret_cast<const float2*>(&x[idx]);
            float2 ov = make_float2(xv.x + o[df][2] * inv1, xv.y + o[df][3] * inv1);
            *reinterpret_cast<float2*>(&g_x1[idx]) = ov;
            __nv_bfloat162 hv = __floats2bfloat162_rn(ov.x, ov.y);
            *reinterpret_cast<__nv_bfloat162*>(&g_x1h[idx]) = hv;
        }
    }
}

// ---------------------------------------------------------------------------
extern "C" void kernel_launch(void* const* d_in, const int* in_sizes, int n_in,
                              void* d_out, int out_size)
{
    const float* x  = (const float*)d_in[0];
    const float* Wq = (const float*)d_in[1];
    const float* Wk = (const float*)d_in[2];
    const float* Wv = (const float*)d_in[3];
    const float* Wf = (const float*)d_in[4];
    const float* bf = (const float*)d_in[5];
    float* out = (float*)d_out;

    cudaFuncSetAttribute((const void*)qkv_gemm, cudaFuncAttributeMaxDynamicSharedMemorySize, BGEMM_SMEM);
    cudaFuncSetAttribute((const void*)ffn_gemm, cudaFuncAttributeMaxDynamicSharedMemorySize, BGEMM_SMEM);
    cudaFuncSetAttribute((const void*)attn_tc,  cudaFuncAttributeMaxDynamicSharedMemorySize, ATTN_SMEM);

    // prologue: single fused f32->bf16 conversion (x + all 4 weights)
    cvt_all_kernel<<<(XN + 4*WN) / 1024, 256>>>(x, Wq, Wk, Wv, Wf);

    // fused QKV projections (bf16 tensor cores): 12 x 32 = 384 CTAs
    qkv_gemm<<<dim3(12, MM/128), 256, BGEMM_SMEM>>>();

    // bf16 flash attention + residual (writes g_x1 f32 + g_x1h bf16)
    attn_tc<<<dim3(TT/QT, BB*HH), 256, ATTN_SMEM>>>(x);

    // bf16 FFN + bias + relu + residual
    ffn_gemm<<<dim3(4, MM/128), 256, BGEMM_SMEM>>>(out, bf);
}

// round 16
// speedup vs baseline: 1.4245x; 1.4245x over previous
#include <cuda_runtime.h>
#include <cuda_bf16.h>
#include <cstdint>
#include <math.h>

#define BB 2
#define TT 2048
#define EE 1024
#define HH 16
#define DH 64
#define MM (BB*TT)   // 4096

// Scratch (__device__ globals; allocations are forbidden)
__device__ float          g_x1[MM*EE];          // attn+residual output (f32, FFN input)
__device__ __nv_bfloat16  g_xh[MM*EE];          // x in bf16 (QKV A operand)
__device__ __nv_bfloat16  g_qh[MM*EE];
__device__ __nv_bfloat16  g_kh[MM*EE];
__device__ __nv_bfloat16  g_vh[MM*EE];
__device__ __nv_bfloat16  g_wh3[3*EE*EE];       // Wq,Wk,Wv bf16, NATURAL [k][n] layout

// ---------------------------------------------------------------------------
// Baseline-PTX helpers (sm_80-era: mma.sync + cp.async + ldmatrix).
// ---------------------------------------------------------------------------
__device__ __forceinline__ uint32_t smem_u32(const void* p){
    uint32_t a;
    asm("{ .reg .u64 t; cvta.to.shared.u64 t, %1; cvt.u32.u64 %0, t; }":"=r"(a):"l"(p));
    return a;
}
#define CP16(dst,src)  asm volatile("cp.async.cg.shared.global [%0], [%1], 16;\n"::"r"(dst),"l"(src))
#define CP_COMMIT()    asm volatile("cp.async.commit_group;\n":::"memory")
#define CP_WAIT1()     asm volatile("cp.async.wait_group 1;\n":::"memory")
#define CP_WAIT0()     asm volatile("cp.async.wait_group 0;\n":::"memory")
#define LDSM4(r0,r1,r2,r3,addr) \
    asm volatile("ldmatrix.sync.aligned.m8n8.x4.shared.b16 {%0,%1,%2,%3}, [%4];" \
        :"=r"(r0),"=r"(r1),"=r"(r2),"=r"(r3):"r"(addr))
#define LDSM4T(r0,r1,r2,r3,addr) \
    asm volatile("ldmatrix.sync.aligned.m8n8.x4.trans.shared.b16 {%0,%1,%2,%3}, [%4];" \
        :"=r"(r0),"=r"(r1),"=r"(r2),"=r"(r3):"r"(addr))

__device__ __forceinline__ void mma_tf32(float c[4], uint32_t a0, uint32_t a1,
                                         uint32_t a2, uint32_t a3,
                                         uint32_t b0, uint32_t b1){
    asm volatile(
        "mma.sync.aligned.m16n8k8.row.col.f32.tf32.tf32.f32 "
        "{%0,%1,%2,%3}, {%4,%5,%6,%7}, {%8,%9}, {%0,%1,%2,%3};\n"
        : "+f"(c[0]), "+f"(c[1]), "+f"(c[2]), "+f"(c[3])
        : "r"(a0), "r"(a1), "r"(a2), "r"(a3), "r"(b0), "r"(b1));
}
__device__ __forceinline__ void mma_bf16(float c[4], uint32_t a0, uint32_t a1,
                                         uint32_t a2, uint32_t a3,
                                         uint32_t b0, uint32_t b1){
    asm volatile(
        "mma.sync.aligned.m16n8k16.row.col.f32.bf16.bf16.f32 "
        "{%0,%1,%2,%3}, {%4,%5,%6,%7}, {%8,%9}, {%0,%1,%2,%3};\n"
        : "+f"(c[0]), "+f"(c[1]), "+f"(c[2]), "+f"(c[3])
        : "r"(a0), "r"(a1), "r"(a2), "r"(a3), "r"(b0), "r"(b1));
}
__device__ __forceinline__ float ex2f(float x){
    float y; asm("ex2.approx.f32 %0, %1;":"=f"(y):"f"(x)); return y;
}

// ---------------------------------------------------------------------------
// Prologue (single launch): f32 -> bf16 for x, Wq, Wk, Wv (no transpose).
// ---------------------------------------------------------------------------
#define XN (MM*EE)     // 4M
#define WN (EE*EE)     // 1M

__global__ void __launch_bounds__(256) cvt_all_kernel(const float* __restrict__ x,
                                                      const float* __restrict__ Wq,
                                                      const float* __restrict__ Wk,
                                                      const float* __restrict__ Wv)
{
    int i = (blockIdx.x * 256 + threadIdx.x) * 4;
    const float* src;
    __nv_bfloat16* dst;
    int off;
    if (i < XN) {
        src = x; dst = g_xh; off = i;
    } else {
        int j = i - XN;
        int slot = j >> 20;              // /WN
        off = j & (WN - 1);
        src = (slot == 0) ? Wq : (slot == 1) ? Wk : Wv;
        dst = g_wh3 + (size_t)slot * WN;
    }
    float4 v = *reinterpret_cast<const float4*>(src + off);
    __nv_bfloat162 p0 = __floats2bfloat162_rn(v.x, v.y);
    __nv_bfloat162 p1 = __floats2bfloat162_rn(v.z, v.w);
    uint2 u;
    u.x = *reinterpret_cast<uint32_t*>(&p0);
    u.y = *reinterpret_cast<uint32_t*>(&p1);
    *reinterpret_cast<uint2*>(&dst[off]) = u;
}

// ---------------------------------------------------------------------------
// bf16 QKV GEMM (fused 3 projections): C = x @ W (proven R12 kernel).
// ---------------------------------------------------------------------------
#define HA_BYTES (128*80)          // 10240
#define WB_ROW   528               // 256 bf16 = 512B + 16B pad
#define WB_BYTES (32*WB_ROW)       // 16896
#define HSTAGE   (HA_BYTES + WB_BYTES)   // 27136
#define QKV_SMEM (2*HSTAGE)        // 54272

__global__ void __launch_bounds__(256) qkv_gemm()
{
    extern __shared__ char smc[];
    const uint32_t sbase = smem_u32(smc);
    const int tid  = threadIdx.x;
    const int wid  = tid >> 5, lane = tid & 31;
    const int ty   = lane >> 2, tx = lane & 3;
    const int wm   = wid >> 2;
    const int wn   = wid & 3;
    const int row0 = blockIdx.y * 128;
    const int sel  = blockIdx.x >> 2;
    const int col0 = (blockIdx.x & 3) * 256;
    const __nv_bfloat16* Wt = g_wh3 + (size_t)sel * WN;   // [k][n]
    __nv_bfloat16* C = (sel == 0) ? g_qh : (sel == 1) ? g_kh : g_vh;

    float c[4][8][4];
    #pragma unroll
    for (int mf = 0; mf < 4; mf++)
        #pragma unroll
        for (int nf = 0; nf < 8; nf++)
            #pragma unroll
            for (int u = 0; u < 4; u++) c[mf][nf][u] = 0.f;

    auto load_tiles = [&](int st, int k0){
        uint32_t sA = sbase + st * HSTAGE;
        uint32_t sB = sA + HA_BYTES;
        #pragma unroll
        for (int t = 0; t < 2; t++) {               // A: 128 rows x 4 chunks (32 bf16)
            int s = tid + t * 256;
            int r = s >> 2, ch = s & 3;
            CP16(sA + (uint32_t)(r * 80 + ch * 16),
                 g_xh + (size_t)(row0 + r) * EE + k0 + ch * 8);
        }
        #pragma unroll
        for (int t = 0; t < 4; t++) {               // B: 32 k-rows x 32 chunks (256 bf16)
            int s = tid + t * 256;
            int r = s >> 5, ch = s & 31;
            CP16(sB + (uint32_t)(r * WB_ROW + ch * 16),
                 Wt + (size_t)(k0 + r) * EE + col0 + ch * 8);
        }
    };

    load_tiles(0, 0);
    CP_COMMIT();

    for (int kt = 0; kt < 32; kt++) {
        const int b = kt & 1;
        if (kt + 1 < 32) {
            load_tiles(1 - b, (kt + 1) << 5);
            CP_COMMIT();
            CP_WAIT1();
        } else {
            CP_WAIT0();
        }
        __syncthreads();

        const uint32_t sA = sbase + b * HSTAGE;
        const uint32_t sB = sA + HA_BYTES;

        #pragma unroll
        for (int ks = 0; ks < 2; ks++) {
            uint32_t a[4][4];
            #pragma unroll
            for (int mf = 0; mf < 4; mf++) {
                uint32_t row = wm * 64 + mf * 16 + (lane & 15);
                uint32_t kh  = ks * 16 + ((lane & 16) >> 1);
                LDSM4(a[mf][0], a[mf][1], a[mf][2], a[mf][3],
                      sA + row * 80 + kh * 2);
            }
            uint32_t bfr[8][2];
            #pragma unroll
            for (int p = 0; p < 4; p++) {
                uint32_t krow = ks * 16 + (lane & 15);
                uint32_t nh   = wn * 64 + p * 16 + ((lane & 16) >> 1);
                LDSM4T(bfr[2*p][0], bfr[2*p][1], bfr[2*p+1][0], bfr[2*p+1][1],
                       sB + krow * WB_ROW + nh * 2);
            }
            #pragma unroll
            for (int mf = 0; mf < 4; mf++)
                #pragma unroll
                for (int nf = 0; nf < 8; nf++)
                    mma_bf16(c[mf][nf], a[mf][0], a[mf][1], a[mf][2], a[mf][3],
                             bfr[nf][0], bfr[nf][1]);
        }
        __syncthreads();
    }

    #pragma unroll
    for (int mf = 0; mf < 4; mf++) {
        const int r = row0 + wm * 64 + mf * 16 + ty;
        #pragma unroll
        for (int nf = 0; nf < 8; nf++) {
            const int cc = col0 + wn * 64 + nf * 8 + (tx << 1);
            __nv_bfloat162 p0 = __floats2bfloat162_rn(c[mf][nf][0], c[mf][nf][1]);
            __nv_bfloat162 p1 = __floats2bfloat162_rn(c[mf][nf][2], c[mf][nf][3]);
            *reinterpret_cast<__nv_bfloat162*>(&C[(size_t)r * EE + cc]) = p0;
            *reinterpret_cast<__nv_bfloat162*>(&C[(size_t)(r + 8) * EE + cc]) = p1;
        }
    }
}

// ---------------------------------------------------------------------------
// bf16 flash attention (proven R12 kernel) + HEAVY-FIRST q-tile ordering:
// qt = gridDim.x-1-blockIdx.x, so long (late-q) tiles are scheduled first
// and the final waves consist of short tiles (LPT makespan reduction).
// ---------------------------------------------------------------------------
#define QT 128
#define AST 72                                  // halfwords per row
#define AT_BYTES (64*AST*2)                     // 9216 per stage
#define ATTN_SMEM (4*AT_BYTES)                  // 36864: KS[2] + VS[2]

__global__ void __launch_bounds__(256, 1) attn_tc(const float* __restrict__ x)
{
    extern __shared__ char smc[];
    const uint32_t sb_KS = smem_u32(smc);               // [2][64][72]h (Q staged here too)
    const uint32_t sb_VS = sb_KS + 2 * AT_BYTES;        // [2][64][72]h

    const int tid = threadIdx.x;
    const int wid = tid >> 5, lane = tid & 31;
    const int ty = lane >> 2, tx = lane & 3;
    const int bh = blockIdx.y, b = bh >> 4, h = bh & 15;
    const int qb = (gridDim.x - 1 - blockIdx.x) * QT;   // heavy-first
    const int ktmax = (qb + QT - 1) >> 6;
    const float sc2 = 0.03125f * 1.44269504088896f;     // 1/sqrt(1024) * log2e

    // ---- stage Q (128 rows x 8 chunks of 16B) through KS area ----
    {
        const __nv_bfloat16* Qg = g_qh + (size_t)(b * TT + qb) * EE + h * DH;
        #pragma unroll
        for (int t = 0; t < 4; t++) {
            int s = tid + t * 256;          // 0..1023
            int r = s >> 3, ch = s & 7;     // 128 rows x 8 chunks
            CP16(sb_KS + (uint32_t)(r * 144 + ch * 16), Qg + (size_t)r * EE + ch * 8);
        }
        CP_COMMIT(); CP_WAIT0();
    }
    __syncthreads();

    uint32_t qa[4][4];
    #pragma unroll
    for (int kf = 0; kf < 4; kf++) {
        uint32_t row = wid * 16 + (lane & 15);
        uint32_t kh  = kf * 16 + ((lane & 16) >> 1);
        LDSM4(qa[kf][0], qa[kf][1], qa[kf][2], qa[kf][3],
              sb_KS + row * 144 + kh * 2);
    }
    __syncthreads();

    float mrow[2] = {-1e30f, -1e30f};
    float lrow[2] = {0.f, 0.f};
    float o[8][4];
    #pragma unroll
    for (int df = 0; df < 8; df++)
        #pragma unroll
        for (int u = 0; u < 4; u++) o[df][u] = 0.f;

    auto issue_tile = [&](int kt){
        const __nv_bfloat16* Kg = g_kh + (size_t)(b * TT + kt * 64) * EE + h * DH;
        const __nv_bfloat16* Vg = g_vh + (size_t)(b * TT + kt * 64) * EE + h * DH;
        uint32_t dK = sb_KS + (uint32_t)((kt & 1) * AT_BYTES);
        uint32_t dV = sb_VS + (uint32_t)((kt & 1) * AT_BYTES);
        #pragma unroll
        for (int t = 0; t < 2; t++) {
            int s = tid + t * 256;          // 0..511
            int r = s >> 3, ch = s & 7;     // 64 rows x 8 chunks
            CP16(dK + (uint32_t)(r * 144 + ch * 16), Kg + (size_t)r * EE + ch * 8);
            CP16(dV + (uint32_t)(r * 144 + ch * 16), Vg + (size_t)r * EE + ch * 8);
        }
        CP_COMMIT();
    };

    issue_tile(0);
    issue_tile(1);

    for (int kt = 0; kt <= ktmax; kt++) {
        const int bs = kt & 1;
        if (kt < ktmax) { CP_WAIT1(); } else { CP_WAIT0(); }
        __syncthreads();

        const uint32_t sK = sb_KS + bs * AT_BYTES;
        const uint32_t sV = sb_VS + bs * AT_BYTES;

        // S = Q K^T (bf16 m16n8k16)
        float s[8][4];
        #pragma unroll
        for (int nf = 0; nf < 8; nf++)
            #pragma unroll
            for (int u = 0; u < 4; u++) s[nf][u] = 0.f;
        #pragma unroll
        for (int kf = 0; kf < 4; kf++) {
            uint32_t bk[8][2];
            #pragma unroll
            for (int p = 0; p < 4; p++) {
                uint32_t row = p * 16 + (lane & 7) + ((lane & 16) >> 1);
                uint32_t kh  = kf * 16 + (lane & 8);
                LDSM4(bk[2*p][0], bk[2*p][1], bk[2*p+1][0], bk[2*p+1][1],
                      sK + row * 144 + kh * 2);
            }
            #pragma unroll
            for (int nf = 0; nf < 8; nf++)
                mma_bf16(s[nf], qa[kf][0], qa[kf][1], qa[kf][2], qa[kf][3],
                         bk[nf][0], bk[nf][1]);
        }

        // scale + causal mask + row max
        const int q0 = qb + wid * 16;
        const bool need_mask = (kt * 64 + 63) > q0;
        float pmax[2] = {-1e30f, -1e30f};
        #pragma unroll
        for (int nf = 0; nf < 8; nf++) {
            int kkb = kt * 64 + nf * 8 + 2 * tx;
            #pragma unroll
            for (int u = 0; u < 4; u++) {
                float v = s[nf][u] * sc2;
                if (need_mask) {
                    int kkg = kkb + (u & 1);
                    int qg  = q0 + ty + ((u >> 1) << 3);
                    if (kkg > qg) v = -1e30f;
                }
                s[nf][u] = v;
                pmax[u >> 1] = fmaxf(pmax[u >> 1], v);
            }
        }
        #pragma unroll
        for (int r = 0; r < 2; r++) {
            pmax[r] = fmaxf(pmax[r], __shfl_xor_sync(0xffffffffu, pmax[r], 1));
            pmax[r] = fmaxf(pmax[r], __shfl_xor_sync(0xffffffffu, pmax[r], 2));
        }
        float mn0 = fmaxf(mrow[0], pmax[0]);
        float mn1 = fmaxf(mrow[1], pmax[1]);
        float cr0 = ex2f(mrow[0] - mn0);
        float cr1 = ex2f(mrow[1] - mn1);
        mrow[0] = mn0; mrow[1] = mn1;

        // P = 2^(s-m): pack bf16 A-frags + row sums
        uint32_t pa[4][4];
        float ls[2] = {0.f, 0.f};
        #pragma unroll
        for (int nf = 0; nf < 8; nf++) {
            float p0 = ex2f(s[nf][0] - mn0);
            float p1 = ex2f(s[nf][1] - mn0);
            float p2 = ex2f(s[nf][2] - mn1);
            float p3 = ex2f(s[nf][3] - mn1);
            ls[0] += p0 + p1;
            ls[1] += p2 + p3;
            __nv_bfloat162 t0 = __floats2bfloat162_rn(p0, p1);
            __nv_bfloat162 t1 = __floats2bfloat162_rn(p2, p3);
            uint32_t lo = *reinterpret_cast<uint32_t*>(&t0);
            uint32_t hi = *reinterpret_cast<uint32_t*>(&t1);
            int kb = nf >> 1;
            if ((nf & 1) == 0) { pa[kb][0] = lo; pa[kb][1] = hi; }
            else               { pa[kb][2] = lo; pa[kb][3] = hi; }
        }
        #pragma unroll
        for (int r = 0; r < 2; r++) {
            ls[r] += __shfl_xor_sync(0xffffffffu, ls[r], 1);
            ls[r] += __shfl_xor_sync(0xffffffffu, ls[r], 2);
        }
        lrow[0] = lrow[0] * cr0 + ls[0];
        lrow[1] = lrow[1] * cr1 + ls[1];

        // rescale O, then O += P @ V  (V via ldmatrix.trans)
        #pragma unroll
        for (int df = 0; df < 8; df++) {
            o[df][0] *= cr0; o[df][1] *= cr0;
            o[df][2] *= cr1; o[df][3] *= cr1;
        }
        #pragma unroll
        for (int kb = 0; kb < 4; kb++) {
            uint32_t vb[8][2];
            #pragma unroll
            for (int dp = 0; dp < 4; dp++) {
                uint32_t row = kb * 16 + (lane & 15);
                uint32_t dhh = dp * 16 + ((lane & 16) >> 1);
                LDSM4T(vb[2*dp][0], vb[2*dp][1], vb[2*dp+1][0], vb[2*dp+1][1],
                       sV + row * 144 + dhh * 2);
            }
            #pragma unroll
            for (int df = 0; df < 8; df++)
                mma_bf16(o[df], pa[kb][0], pa[kb][1], pa[kb][2], pa[kb][3],
                         vb[df][0], vb[df][1]);
        }
        __syncthreads();
        if (kt + 2 <= ktmax) issue_tile(kt + 2);
    }

    // epilogue: normalize + residual
    const float inv0 = 1.f / lrow[0];
    const float inv1 = 1.f / lrow[1];
    const size_t base = (size_t)(b * TT + qb + wid * 16) * EE + h * DH;
    #pragma unroll
    for (int df = 0; df < 8; df++) {
        int col = df * 8 + 2 * tx;
        {
            size_t idx = base + (size_t)ty * EE + col;
            float2 xv = *reinterpret_cast<const float2*>(&x[idx]);
            float2 ov = make_float2(xv.x + o[df][0] * inv0, xv.y + o[df][1] * inv0);
            *reinterpret_cast<float2*>(&g_x1[idx]) = ov;
        }
        {
            size_t idx = base + (size_t)(ty + 8) * EE + col;
            float2 xv = *reinterpret_cast<const float2*>(&x[idx]);
            float2 ov = make_float2(xv.x + o[df][2] * inv1, xv.y + o[df][3] * inv1);
            *reinterpret_cast<float2*>(&g_x1[idx]) = ov;
        }
    }
}

// ---------------------------------------------------------------------------
// FFN GEMM: proven tf32 path (precision-critical; stays tf32 permanently —
// the R14 bf16 experiment tripled rel_err and was slower).
// out = x1 + relu(x1 @ Wf + bias). CTA 128x256, BK=32.
// ---------------------------------------------------------------------------
#define A_ST 36
#define B_ST 264
#define A_TILE (128*A_ST)
#define B_TILE (32*B_ST)
#define STAGE  (A_TILE + B_TILE)
#define GEMM_SMEM (2*STAGE*4)

__global__ void __launch_bounds__(256) ffn_gemm(const float* __restrict__ A,
                                                const float* __restrict__ W,
                                                float* __restrict__ C,
                                                const float* __restrict__ bias)
{
    extern __shared__ float sm[];
    const uint32_t sbase = smem_u32(sm);
    const int tid  = threadIdx.x;
    const int wid  = tid >> 5, lane = tid & 31;
    const int ty   = lane >> 2, tx = lane & 3;
    const int wm   = wid >> 2;
    const int wn   = wid & 3;
    const int row0 = blockIdx.y * 128;
    const int col0 = blockIdx.x * 256;

    float c[4][8][4];
    #pragma unroll
    for (int mf = 0; mf < 4; mf++)
        #pragma unroll
        for (int nf = 0; nf < 8; nf++)
            #pragma unroll
            for (int u = 0; u < 4; u++) c[mf][nf][u] = 0.f;

    auto load_tiles = [&](int st, int k0){
        uint32_t sA = sbase + st * (STAGE * 4);
        uint32_t sB = sA + A_TILE * 4;
        #pragma unroll
        for (int t = 0; t < 4; t++) {
            int s  = tid + t * 256;
            int r  = s >> 3;
            int cf = (s & 7) << 2;
            CP16(sA + (uint32_t)(r * A_ST + cf) * 4,
                 A + (size_t)(row0 + r) * EE + k0 + cf);
        }
        #pragma unroll
        for (int t = 0; t < 8; t++) {
            int s  = tid + t * 256;
            int r  = s >> 6;
            int cf = (s & 63) << 2;
            CP16(sB + (uint32_t)(r * B_ST + cf) * 4,
                 W + (size_t)(k0 + r) * EE + col0 + cf);
        }
    };

    load_tiles(0, 0);
    CP_COMMIT();

    for (int kt = 0; kt < 32; kt++) {
        const int b = kt & 1;
        if (kt + 1 < 32) {
            load_tiles(1 - b, (kt + 1) << 5);
            CP_COMMIT();
            CP_WAIT1();
        } else {
            CP_WAIT0();
        }
        __syncthreads();

        const float* As = sm + b * STAGE;
        const float* Bs = As + A_TILE;

        #pragma unroll
        for (int ks = 0; ks < 4; ks++) {
            const int k = ks << 3;
            uint32_t a[4][4];
            #pragma unroll
            for (int mf = 0; mf < 4; mf++) {
                const int rb = wm * 64 + mf * 16;
                a[mf][0] = __float_as_uint(As[(rb + ty    ) * A_ST + k + tx    ]);
                a[mf][1] = __float_as_uint(As[(rb + ty + 8) * A_ST + k + tx    ]);
                a[mf][2] = __float_as_uint(As[(rb + ty    ) * A_ST + k + tx + 4]);
                a[mf][3] = __float_as_uint(As[(rb + ty + 8) * A_ST + k + tx + 4]);
            }
            uint32_t bfr[8][2];
            #pragma unroll
            for (int nf = 0; nf < 8; nf++) {
                const int n = wn * 64 + nf * 8 + ty;
                bfr[nf][0] = __float_as_uint(Bs[(k + tx    ) * B_ST + n]);
                bfr[nf][1] = __float_as_uint(Bs[(k + tx + 4) * B_ST + n]);
            }
            #pragma unroll
            for (int mf = 0; mf < 4; mf++)
                #pragma unroll
                for (int nf = 0; nf < 8; nf++)
                    mma_tf32(c[mf][nf], a[mf][0], a[mf][1], a[mf][2], a[mf][3],
                             bfr[nf][0], bfr[nf][1]);
        }
        __syncthreads();
    }

    #pragma unroll
    for (int mf = 0; mf < 4; mf++) {
        const int r = row0 + wm * 64 + mf * 16 + ty;
        #pragma unroll
        for (int nf = 0; nf < 8; nf++) {
            const int cc = col0 + wn * 64 + nf * 8 + (tx << 1);
            float2 v0 = make_float2(c[mf][nf][0], c[mf][nf][1]);
            float2 v1 = make_float2(c[mf][nf][2], c[mf][nf][3]);
            float2 bb = *reinterpret_cast<const float2*>(bias + cc);
            float2 x0 = *reinterpret_cast<const float2*>(A + (size_t)r * EE + cc);
            float2 x1 = *reinterpret_cast<const float2*>(A + (size_t)(r + 8) * EE + cc);
            v0.x = x0.x + fmaxf(v0.x + bb.x, 0.f);
            v0.y = x0.y + fmaxf(v0.y + bb.y, 0.f);
            v1.x = x1.x + fmaxf(v1.x + bb.x, 0.f);
            v1.y = x1.y + fmaxf(v1.y + bb.y, 0.f);
            *reinterpret_cast<float2*>(C + (size_t)r * EE + cc) = v0;
            *reinterpret_cast<float2*>(C + (size_t)(r + 8) * EE + cc) = v1;
        }
    }
}

// ---------------------------------------------------------------------------
extern "C" void kernel_launch(void* const* d_in, const int* in_sizes, int n_in,
                              void* d_out, int out_size)
{
    const float* x  = (const float*)d_in[0];
    const float* Wq = (const float*)d_in[1];
    const float* Wk = (const float*)d_in[2];
    const float* Wv = (const float*)d_in[3];
    const float* Wf = (const float*)d_in[4];
    const float* bf = (const float*)d_in[5];
    float* out = (float*)d_out;

    float* gx1;
    cudaGetSymbolAddress((void**)&gx1, g_x1);

    cudaFuncSetAttribute((const void*)qkv_gemm, cudaFuncAttributeMaxDynamicSharedMemorySize, QKV_SMEM);
    cudaFuncSetAttribute((const void*)attn_tc,  cudaFuncAttributeMaxDynamicSharedMemorySize, ATTN_SMEM);
    cudaFuncSetAttribute((const void*)ffn_gemm, cudaFuncAttributeMaxDynamicSharedMemorySize, GEMM_SMEM);

    // prologue: single fused f32->bf16 conversion (x + Wq + Wk + Wv)
    cvt_all_kernel<<<(XN + 3*WN) / 1024, 256>>>(x, Wq, Wk, Wv);

    // fused QKV projections (bf16 tensor cores): 12 x 32 = 384 CTAs
    qkv_gemm<<<dim3(12, MM/128), 256, QKV_SMEM>>>();

    // bf16 flash attention + residual (heavy-first q-tile order)
    attn_tc<<<dim3(TT/QT, BB*HH), 256, ATTN_SMEM>>>(x);

    // FFN (tf32) + bias + relu + residual
    ffn_gemm<<<dim3(4, MM/128), 256, GEMM_SMEM>>>(gx1, Wf, out, bf);
}